// round 1
// baseline (speedup 1.0000x reference)
#include <cuda_runtime.h>
#include <math.h>

#define MAXN 100000
#define MAXE 1600000

// ---------------- scratch (static device globals; no allocation) ------------
__device__ __align__(16) float g_agg[(size_t)MAXN * 64];
__device__ __align__(16) float g_h1[(size_t)MAXN * 64];
__device__ __align__(16) float g_h2[(size_t)MAXN * 64];
__device__ float g_deg[MAXN];
__device__ float g_inv[MAXN];
__device__ float g_s[MAXN];
__device__ float g_t[MAXN];
__device__ float g_aggS[MAXN];
__device__ int   g_src[MAXE];
__device__ int   g_dst[MAXE];
__device__ int   g_is64;

// ---------------- dtype detect: int64 vs int32 edge_index -------------------
__global__ void k_detect(const int* __restrict__ ei32) {
    int is64 = 1;
#pragma unroll
    for (int i = 1; i < 32; i += 2)
        if (ei32[i] != 0) is64 = 0;
    g_is64 = is64;
}

// ---------------- zero deg/aggS + agg (layer-1 region, N*32) ----------------
__global__ void k_zero_pre(int N) {
    long tot = (long)N * 32;
    for (long i = blockIdx.x * (long)blockDim.x + threadIdx.x; i < tot;
         i += (long)gridDim.x * blockDim.x) {
        g_agg[i] = 0.0f;
        if (i < N) { g_deg[i] = 0.0f; g_aggS[i] = 0.0f; }
    }
}

__global__ void k_zero_agg64(int N) {
    long tot = (long)N * 64;
    for (long i = blockIdx.x * (long)blockDim.x + threadIdx.x; i < tot;
         i += (long)gridDim.x * blockDim.x)
        g_agg[i] = 0.0f;
}

// ---------------- convert edge_index -> int32 src/dst, degree histogram -----
__global__ void k_convert(const void* __restrict__ ei, int E) {
    int is64 = g_is64;
    for (int e = blockIdx.x * blockDim.x + threadIdx.x; e < E;
         e += gridDim.x * blockDim.x) {
        int s, d;
        if (is64) {
            const long long* p = (const long long*)ei;
            s = (int)p[e];
            d = (int)p[(long)E + e];
        } else {
            const int* p = (const int*)ei;
            s = p[e];
            d = p[(long)E + e];
        }
        g_src[e] = s;
        g_dst[e] = d;
        atomicAdd(&g_deg[d], 1.0f);
    }
}

__global__ void k_inv(int N) {
    for (int i = blockIdx.x * blockDim.x + threadIdx.x; i < N;
         i += gridDim.x * blockDim.x)
        g_inv[i] = 1.0f / fmaxf(g_deg[i], 1.0f);
}

// ---------------- edge aggregation: sum_{j in N(i)} feat[j] -----------------
// C/4 lanes per edge; float4 gather + red.global.add.v4.f32 scatter.
template <int C>
__global__ void k_agg(const float* __restrict__ featx, int E) {
    const float* feat = (C == 32) ? featx : g_h1;
    constexpr int G = C / 4;
    long tot = (long)E * G;
    for (long t = blockIdx.x * (long)blockDim.x + threadIdx.x; t < tot;
         t += (long)gridDim.x * blockDim.x) {
        int e = (int)(t / G);
        int c = (int)(t % G);
        int s = g_src[e];
        int d = g_dst[e];
        float4 v = ((const float4*)(feat + (long)s * C))[c];
        float* ap = g_agg + (long)d * C + c * 4;
        asm volatile("red.global.add.v4.f32 [%0], {%1,%2,%3,%4};"
                     :: "l"(ap), "f"(v.x), "f"(v.y), "f"(v.z), "f"(v.w)
                     : "memory");
    }
}

// ---------------- fused SAGE layer GEMM + bias + relu -----------------------
// out[n][o] = relu( sum_k agg[n][k]*inv[n]*wl[o][k] + fb[n][k]*wr[o][k] + b[o] )
// Thread tiling: 4 nodes x 16 outputs per thread; weights staged in SMEM.
template <int KH, int LAYER>
__global__ void k_gemm(const float* __restrict__ fbx,
                       const float* __restrict__ wl,
                       const float* __restrict__ wr,
                       const float* __restrict__ bias, int N) {
    constexpr int COUT = 64, OT = 16;
    const float* fb = (LAYER == 1) ? fbx : g_h1;
    float* out = (LAYER == 1) ? g_h1 : g_h2;

    __shared__ float swl[KH][COUT];
    __shared__ float swr[KH][COUT];
    for (int i = threadIdx.x; i < KH * COUT; i += blockDim.x) {
        int o = i / KH, k = i % KH;
        swl[k][o] = wl[i];
        swr[k][o] = wr[i];
    }
    __syncthreads();

    int og = (threadIdx.x & 3) * OT;
    int nb = blockIdx.x * 128 + (threadIdx.x >> 2) * 4;
    if (nb >= N) return;

    int idx[4];
    float iv[4];
#pragma unroll
    for (int i = 0; i < 4; i++) {
        idx[i] = min(nb + i, N - 1);
        iv[i] = g_inv[idx[i]];
    }

    float acc[4][OT];
#pragma unroll
    for (int i = 0; i < 4; i++)
#pragma unroll
        for (int j = 0; j < OT; j++) acc[i][j] = 0.0f;

    for (int k = 0; k < KH; k++) {
        float va[4], vb[4];
#pragma unroll
        for (int i = 0; i < 4; i++) {
            va[i] = g_agg[(long)idx[i] * KH + k] * iv[i];
            vb[i] = fb[(long)idx[i] * KH + k];
        }
#pragma unroll
        for (int j = 0; j < OT; j++) {
            float wlv = swl[k][og + j];
            float wrv = swr[k][og + j];
#pragma unroll
            for (int i = 0; i < 4; i++)
                acc[i][j] += va[i] * wlv + vb[i] * wrv;
        }
    }

#pragma unroll
    for (int i = 0; i < 4; i++) {
        if (nb + i >= N) break;
#pragma unroll
        for (int j = 0; j < OT; j++) {
            float v = acc[i][j] + bias[og + j];
            out[(long)(nb + i) * COUT + og + j] = fmaxf(v, 0.0f);
        }
    }
}

// ---------------- layer-3 scalar projections: s=wl3.h2, t=wr3.h2 ------------
__global__ void k_proj3(const float* __restrict__ wl3,
                        const float* __restrict__ wr3, int N) {
    __shared__ float sl[64], sr[64];
    if (threadIdx.x < 64) {
        sl[threadIdx.x] = wl3[threadIdx.x];
        sr[threadIdx.x] = wr3[threadIdx.x];
    }
    __syncthreads();
    for (int n = blockIdx.x * blockDim.x + threadIdx.x; n < N;
         n += gridDim.x * blockDim.x) {
        const float4* row = (const float4*)(g_h2 + (long)n * 64);
        float s = 0.0f, t = 0.0f;
#pragma unroll
        for (int q = 0; q < 16; q++) {
            float4 v = row[q];
            s += v.x * sl[4 * q] + v.y * sl[4 * q + 1] +
                 v.z * sl[4 * q + 2] + v.w * sl[4 * q + 3];
            t += v.x * sr[4 * q] + v.y * sr[4 * q + 1] +
                 v.z * sr[4 * q + 2] + v.w * sr[4 * q + 3];
        }
        g_s[n] = s;
        g_t[n] = t;
    }
}

// ---------------- layer-3 scalar edge aggregation ---------------------------
__global__ void k_aggS(int E) {
    for (int e = blockIdx.x * blockDim.x + threadIdx.x; e < E;
         e += gridDim.x * blockDim.x)
        atomicAdd(&g_aggS[g_dst[e]], g_s[g_src[e]]);
}

// ---------------- final: sigmoid(mean_s + b3 + t) ----------------------------
__global__ void k_final(const float* __restrict__ b3, float* __restrict__ out,
                        int N) {
    for (int n = blockIdx.x * blockDim.x + threadIdx.x; n < N;
         n += gridDim.x * blockDim.x) {
        float z = g_aggS[n] * g_inv[n] + b3[0] + g_t[n];
        out[n] = 1.0f / (1.0f + expf(-z));
    }
}

// ---------------- launch -----------------------------------------------------
extern "C" void kernel_launch(void* const* d_in, const int* in_sizes, int n_in,
                              void* d_out, int out_size) {
    const float* x   = (const float*)d_in[0];
    const void*  ei  = d_in[1];
    const float* wl1 = (const float*)d_in[2];
    const float* wr1 = (const float*)d_in[3];
    const float* b1  = (const float*)d_in[4];
    const float* wl2 = (const float*)d_in[5];
    const float* wr2 = (const float*)d_in[6];
    const float* b2  = (const float*)d_in[7];
    const float* wl3 = (const float*)d_in[8];
    const float* wr3 = (const float*)d_in[9];
    const float* b3  = (const float*)d_in[10];
    float* out = (float*)d_out;

    int N = in_sizes[0] / 32;
    int E = in_sizes[1] / 2;

    k_detect<<<1, 1>>>((const int*)ei);
    {
        long tot = (long)N * 32;
        int blocks = (int)((tot + 255) / 256);
        k_zero_pre<<<blocks, 256>>>(N);
    }
    k_convert<<<(E + 255) / 256, 256>>>(ei, E);
    k_inv<<<(N + 255) / 256, 256>>>(N);

    // ---- layer 1 ----
    {
        long tot = (long)E * 8;
        k_agg<32><<<(int)((tot + 255) / 256), 256>>>(x, E);
    }
    k_gemm<32, 1><<<(N + 127) / 128, 128>>>(x, wl1, wr1, b1, N);

    // ---- layer 2 ----
    {
        long tot = (long)N * 64;
        k_zero_agg64<<<(int)((tot + 255) / 256), 256>>>(N);
    }
    {
        long tot = (long)E * 16;
        k_agg<64><<<(int)((tot + 255) / 256), 256>>>(nullptr, E);
    }
    k_gemm<64, 2><<<(N + 127) / 128, 128>>>(nullptr, wl2, wr2, b2, N);

    // ---- layer 3 (fused: project to scalar, aggregate scalars) ----
    k_proj3<<<(N + 255) / 256, 256>>>(wl3, wr3, N);
    k_aggS<<<(E + 255) / 256, 256>>>(E);
    k_final<<<(N + 255) / 256, 256>>>(b3, out, N);
}

// round 3
// speedup vs baseline: 1.2893x; 1.2893x over previous
#include <cuda_runtime.h>
#include <math.h>

#define MAXN 100000
#define MAXE 1600000
#define SCAN_CH 512
#define MAXNB 256   // >= ceil(MAXN/SCAN_CH) = 196

// ---------------- scratch (static device globals; no allocation) ------------
// NOTE: these are ONLY referenced from device code. Passing a __device__
// symbol as a host-side kernel argument silently binds the host shadow
// address (ATS makes it "work" but touch host memory) — root cause of the
// round-2 accuracy failure.
__device__ __align__(16) float g_agg[(size_t)MAXN * 64];  // mean features
__device__ __align__(16) float g_h1[(size_t)MAXN * 64];
__device__ __align__(16) float g_h2[(size_t)MAXN * 64];
__device__ float g_inv[MAXN];
__device__ float g_s[MAXN];
__device__ float g_t[MAXN];
__device__ int   g_degi[MAXN];
__device__ int   g_off[MAXN];
__device__ int   g_cur[MAXN];
__device__ int   g_csr[MAXE];
__device__ int   g_part[MAXNB];
__device__ int   g_pscan[MAXNB];
__device__ int   g_is64;

// ---------------- dtype detect: int64 vs int32 edge_index -------------------
__global__ void k_detect(const int* __restrict__ ei32) {
    int is64 = 1;
#pragma unroll
    for (int i = 1; i < 32; i += 2)
        if (ei32[i] != 0) is64 = 0;
    g_is64 = is64;
}

__global__ void k_zero_degi(int N) {
    for (int i = blockIdx.x * blockDim.x + threadIdx.x; i < N;
         i += gridDim.x * blockDim.x)
        g_degi[i] = 0;
}

// ---------------- degree histogram ------------------------------------------
__global__ void k_count(const void* __restrict__ ei, int E) {
    int is64 = g_is64;
    for (int e = blockIdx.x * blockDim.x + threadIdx.x; e < E;
         e += gridDim.x * blockDim.x) {
        int d;
        if (is64) d = (int)((const long long*)ei)[(long)E + e];
        else      d = ((const int*)ei)[(long)E + e];
        atomicAdd(&g_degi[d], 1);
    }
}

// ---------------- 3-phase exclusive scan of degrees -------------------------
__global__ void k_scan1(int N) {
    __shared__ int s[SCAN_CH];
    int tid = threadIdx.x;
    int n = blockIdx.x * SCAN_CH + tid;
    s[tid] = (n < N) ? g_degi[n] : 0;
    __syncthreads();
    for (int ofs = SCAN_CH / 2; ofs > 0; ofs >>= 1) {
        if (tid < ofs) s[tid] += s[tid + ofs];
        __syncthreads();
    }
    if (tid == 0) g_part[blockIdx.x] = s[0];
}

__global__ void k_scan2(int NB) {
    __shared__ int s[MAXNB];
    int tid = threadIdx.x;
    int v = (tid < NB) ? g_part[tid] : 0;
    s[tid] = v;
    __syncthreads();
    for (int ofs = 1; ofs < MAXNB; ofs <<= 1) {
        int t = (tid >= ofs) ? s[tid - ofs] : 0;
        __syncthreads();
        s[tid] += t;
        __syncthreads();
    }
    if (tid < NB) g_pscan[tid] = s[tid] - v;
}

__global__ void k_scan3(int N) {
    __shared__ int s[SCAN_CH];
    int tid = threadIdx.x;
    int n = blockIdx.x * SCAN_CH + tid;
    int dg = (n < N) ? g_degi[n] : 0;
    s[tid] = dg;
    __syncthreads();
    for (int ofs = 1; ofs < SCAN_CH; ofs <<= 1) {
        int t = (tid >= ofs) ? s[tid - ofs] : 0;
        __syncthreads();
        s[tid] += t;
        __syncthreads();
    }
    if (n < N) {
        int off = g_pscan[blockIdx.x] + s[tid] - dg;
        g_off[n] = off;
        g_cur[n] = off;
        g_inv[n] = 1.0f / fmaxf((float)dg, 1.0f);
    }
}

// ---------------- CSR fill ----------------------------------------------------
__global__ void k_fill(const void* __restrict__ ei, int E) {
    int is64 = g_is64;
    for (int e = blockIdx.x * blockDim.x + threadIdx.x; e < E;
         e += gridDim.x * blockDim.x) {
        int sN, d;
        if (is64) {
            const long long* p = (const long long*)ei;
            sN = (int)p[e];
            d = (int)p[(long)E + e];
        } else {
            const int* p = (const int*)ei;
            sN = p[e];
            d = p[(long)E + e];
        }
        int pos = atomicAdd(&g_cur[d], 1);
        g_csr[pos] = sN;
    }
}

// ---------------- gather-side mean aggregation (warp per node) ---------------
// C=32: feat = external x (harness pointer). C=64: feat = g_h1 (device global,
// selected INSIDE device code). Output always g_agg.
template <int C>
__global__ void k_aggmean(const float* __restrict__ featx, int N) {
    int warp = (blockIdx.x * blockDim.x + threadIdx.x) >> 5;
    int lane = threadIdx.x & 31;
    if (warp >= N) return;
    int n = warp;
    int beg = g_off[n];
    int end = beg + g_degi[n];
    float iv = g_inv[n];

    if (C == 64) {
        const float2* f2 = (const float2*)g_h1;
        float2 acc = make_float2(0.0f, 0.0f);
        int j = beg;
        for (; j + 1 < end; j += 2) {
            int s0 = g_csr[j], s1 = g_csr[j + 1];
            float2 a = f2[(long)s0 * 32 + lane];
            float2 b = f2[(long)s1 * 32 + lane];
            acc.x += a.x + b.x;
            acc.y += a.y + b.y;
        }
        if (j < end) {
            int s0 = g_csr[j];
            float2 a = f2[(long)s0 * 32 + lane];
            acc.x += a.x;
            acc.y += a.y;
        }
        ((float2*)g_agg)[(long)n * 32 + lane] =
            make_float2(acc.x * iv, acc.y * iv);
    } else {  // C == 32
        const float* feat = featx;
        float acc = 0.0f;
        int j = beg;
        for (; j + 1 < end; j += 2) {
            int s0 = g_csr[j], s1 = g_csr[j + 1];
            acc += feat[(long)s0 * 32 + lane] + feat[(long)s1 * 32 + lane];
        }
        if (j < end) acc += feat[(long)g_csr[j] * 32 + lane];
        g_agg[(long)n * 32 + lane] = acc * iv;
    }
}

// ---------------- fused SAGE layer GEMM + bias + relu -----------------------
// out[n][o] = relu( sum_k mean[n][k]*wl[o][k] + fb[n][k]*wr[o][k] + b[o] )
template <int KH, int LAYER>
__global__ void k_gemm(const float* __restrict__ fbx,
                       const float* __restrict__ wl,
                       const float* __restrict__ wr,
                       const float* __restrict__ bias, int N) {
    constexpr int COUT = 64, OT = 16;
    const float* fb = (LAYER == 1) ? fbx : g_h1;
    float* out = (LAYER == 1) ? g_h1 : g_h2;

    __shared__ float swl[KH][COUT];
    __shared__ float swr[KH][COUT];
    for (int i = threadIdx.x; i < KH * COUT; i += blockDim.x) {
        int o = i / KH, k = i % KH;
        swl[k][o] = wl[i];
        swr[k][o] = wr[i];
    }
    __syncthreads();

    int og = (threadIdx.x & 3) * OT;
    int nb = blockIdx.x * 128 + (threadIdx.x >> 2) * 4;
    if (nb >= N) return;

    int idx[4];
#pragma unroll
    for (int i = 0; i < 4; i++) idx[i] = min(nb + i, N - 1);

    float acc[4][OT];
#pragma unroll
    for (int i = 0; i < 4; i++)
#pragma unroll
        for (int j = 0; j < OT; j++) acc[i][j] = 0.0f;

    for (int k = 0; k < KH; k++) {
        float va[4], vb[4];
#pragma unroll
        for (int i = 0; i < 4; i++) {
            va[i] = g_agg[(long)idx[i] * KH + k];
            vb[i] = fb[(long)idx[i] * KH + k];
        }
#pragma unroll
        for (int j = 0; j < OT; j++) {
            float wlv = swl[k][og + j];
            float wrv = swr[k][og + j];
#pragma unroll
            for (int i = 0; i < 4; i++)
                acc[i][j] += va[i] * wlv + vb[i] * wrv;
        }
    }

#pragma unroll
    for (int i = 0; i < 4; i++) {
        if (nb + i >= N) break;
#pragma unroll
        for (int j = 0; j < OT; j++) {
            float v = acc[i][j] + bias[og + j];
            out[(long)(nb + i) * COUT + og + j] = fmaxf(v, 0.0f);
        }
    }
}

// ---------------- layer-3 scalar projections: s=wl3.h2, t=wr3.h2 ------------
__global__ void k_proj3(const float* __restrict__ wl3,
                        const float* __restrict__ wr3, int N) {
    __shared__ float sl[64], sr[64];
    if (threadIdx.x < 64) {
        sl[threadIdx.x] = wl3[threadIdx.x];
        sr[threadIdx.x] = wr3[threadIdx.x];
    }
    __syncthreads();
    for (int n = blockIdx.x * blockDim.x + threadIdx.x; n < N;
         n += gridDim.x * blockDim.x) {
        const float4* row = (const float4*)(g_h2 + (long)n * 64);
        float s = 0.0f, t = 0.0f;
#pragma unroll
        for (int q = 0; q < 16; q++) {
            float4 v = row[q];
            s += v.x * sl[4 * q] + v.y * sl[4 * q + 1] +
                 v.z * sl[4 * q + 2] + v.w * sl[4 * q + 3];
            t += v.x * sr[4 * q] + v.y * sr[4 * q + 1] +
                 v.z * sr[4 * q + 2] + v.w * sr[4 * q + 3];
        }
        g_s[n] = s;
        g_t[n] = t;
    }
}

// ---------------- layer-3: CSR scalar aggregation + sigmoid (fused) ---------
__global__ void k_out3(const float* __restrict__ b3, float* __restrict__ out,
                       int N) {
    int warp = (blockIdx.x * blockDim.x + threadIdx.x) >> 5;
    int lane = threadIdx.x & 31;
    if (warp >= N) return;
    int n = warp;
    int beg = g_off[n];
    int end = beg + g_degi[n];
    float acc = 0.0f;
    for (int j = beg + lane; j < end; j += 32) acc += g_s[g_csr[j]];
#pragma unroll
    for (int o = 16; o > 0; o >>= 1)
        acc += __shfl_xor_sync(0xffffffffu, acc, o);
    if (lane == 0) {
        float z = acc * g_inv[n] + b3[0] + g_t[n];
        out[n] = 1.0f / (1.0f + expf(-z));
    }
}

// ---------------- launch -----------------------------------------------------
extern "C" void kernel_launch(void* const* d_in, const int* in_sizes, int n_in,
                              void* d_out, int out_size) {
    const float* x   = (const float*)d_in[0];
    const void*  ei  = d_in[1];
    const float* wl1 = (const float*)d_in[2];
    const float* wr1 = (const float*)d_in[3];
    const float* b1  = (const float*)d_in[4];
    const float* wl2 = (const float*)d_in[5];
    const float* wr2 = (const float*)d_in[6];
    const float* b2  = (const float*)d_in[7];
    const float* wl3 = (const float*)d_in[8];
    const float* wr3 = (const float*)d_in[9];
    const float* b3  = (const float*)d_in[10];
    float* out = (float*)d_out;

    int N = in_sizes[0] / 32;
    int E = in_sizes[1] / 2;
    int NB = (N + SCAN_CH - 1) / SCAN_CH;

    // ---- preprocessing: CSR build ----
    k_detect<<<1, 1>>>((const int*)ei);
    k_zero_degi<<<(N + 255) / 256, 256>>>(N);
    k_count<<<(E + 255) / 256, 256>>>(ei, E);
    k_scan1<<<NB, SCAN_CH>>>(N);
    k_scan2<<<1, MAXNB>>>(NB);
    k_scan3<<<NB, SCAN_CH>>>(N);
    k_fill<<<(E + 255) / 256, 256>>>(ei, E);

    // ---- layer 1 ----
    k_aggmean<32><<<(N * 32 + 255) / 256, 256>>>(x, N);
    k_gemm<32, 1><<<(N + 127) / 128, 128>>>(x, wl1, wr1, b1, N);

    // ---- layer 2 ----
    k_aggmean<64><<<(N * 32 + 255) / 256, 256>>>(nullptr, N);
    k_gemm<64, 2><<<(N + 127) / 128, 128>>>(nullptr, wl2, wr2, b2, N);

    // ---- layer 3 (scalar-fused) ----
    k_proj3<<<(N + 255) / 256, 256>>>(wl3, wr3, N);
    k_out3<<<(N * 32 + 255) / 256, 256>>>(b3, out, N);
}

// round 4
// speedup vs baseline: 1.4481x; 1.1232x over previous
#include <cuda_runtime.h>
#include <math.h>

#define MAXN 100000
#define MAXE 1600000
#define SCAN_CH 512
#define MAXNB 256   // >= ceil(MAXN/SCAN_CH) = 196

// ---------------- scratch (device-code-only globals; see round-2 postmortem)
__device__ __align__(16) float g_agg[(size_t)MAXN * 64];
__device__ __align__(16) float g_h1[(size_t)MAXN * 64];
__device__ float g_inv[MAXN];
__device__ float g_s[MAXN];
__device__ float g_t[MAXN];
__device__ int   g_degi[MAXN];
__device__ int   g_off[MAXN];
__device__ int   g_cur[MAXN];
__device__ int   g_csr[MAXE];
__device__ int   g_part[MAXNB];
__device__ int   g_pscan[MAXNB];
__device__ int   g_is64;

// ---------------- packed f32x2 helpers ---------------------------------------
__device__ __forceinline__ unsigned long long pack2(float x, float y) {
    unsigned long long r;
    asm("mov.b64 %0, {%1, %2};" : "=l"(r) : "f"(x), "f"(y));
    return r;
}
__device__ __forceinline__ void fma2(unsigned long long& d,
                                     unsigned long long a,
                                     unsigned long long b) {
    asm("fma.rn.f32x2 %0, %1, %2, %0;" : "+l"(d) : "l"(a), "l"(b));
}
__device__ __forceinline__ float2 unpack2(unsigned long long r) {
    float2 f;
    asm("mov.b64 {%0, %1}, %2;" : "=f"(f.x), "=f"(f.y) : "l"(r));
    return f;
}

// ---------------- dtype detect: int64 vs int32 edge_index -------------------
__global__ void k_detect(const int* __restrict__ ei32) {
    int is64 = 1;
#pragma unroll
    for (int i = 1; i < 32; i += 2)
        if (ei32[i] != 0) is64 = 0;
    g_is64 = is64;
}

__global__ void k_zero_degi(int N) {
    for (int i = blockIdx.x * blockDim.x + threadIdx.x; i < N;
         i += gridDim.x * blockDim.x)
        g_degi[i] = 0;
}

// ---------------- degree histogram ------------------------------------------
__global__ void k_count(const void* __restrict__ ei, int E) {
    int is64 = g_is64;
    for (int e = blockIdx.x * blockDim.x + threadIdx.x; e < E;
         e += gridDim.x * blockDim.x) {
        int d;
        if (is64) d = (int)((const long long*)ei)[(long)E + e];
        else      d = ((const int*)ei)[(long)E + e];
        atomicAdd(&g_degi[d], 1);
    }
}

// ---------------- scan phase 1: per-chunk sums (warp shuffles) --------------
__global__ void k_scan1(int N) {
    __shared__ int sw[16];
    int tid = threadIdx.x;
    int n = blockIdx.x * SCAN_CH + tid;
    int v = (n < N) ? g_degi[n] : 0;
#pragma unroll
    for (int o = 16; o > 0; o >>= 1) v += __shfl_xor_sync(0xffffffffu, v, o);
    if ((tid & 31) == 0) sw[tid >> 5] = v;
    __syncthreads();
    if (tid < 16) {
        int t = sw[tid];
#pragma unroll
        for (int o = 8; o > 0; o >>= 1)
            t += __shfl_xor_sync(0x0000ffffu, t, o, 16);
        if (tid == 0) g_part[blockIdx.x] = t;
    }
}

// ---------------- scan phase 2: scan of 196 partials -------------------------
__global__ void k_scan2(int NB) {
    __shared__ int s[MAXNB];
    int tid = threadIdx.x;
    int v = (tid < NB) ? g_part[tid] : 0;
    s[tid] = v;
    __syncthreads();
    for (int ofs = 1; ofs < MAXNB; ofs <<= 1) {
        int t = (tid >= ofs) ? s[tid - ofs] : 0;
        __syncthreads();
        s[tid] += t;
        __syncthreads();
    }
    if (tid < NB) g_pscan[tid] = s[tid] - v;
}

// ---------------- scan phase 3: intra-chunk exclusive scan (shuffles) -------
__global__ void k_scan3(int N) {
    __shared__ int sw[16];
    int tid = threadIdx.x;
    int lane = tid & 31, wid = tid >> 5;
    int n = blockIdx.x * SCAN_CH + tid;
    int dg = (n < N) ? g_degi[n] : 0;
    int v = dg;
#pragma unroll
    for (int o = 1; o < 32; o <<= 1) {
        int t = __shfl_up_sync(0xffffffffu, v, o);
        if (lane >= o) v += t;
    }
    if (lane == 31) sw[wid] = v;
    __syncthreads();
    if (wid == 0 && lane < 16) {
        int t = sw[lane];
        int u = t;
#pragma unroll
        for (int o = 1; o < 16; o <<= 1) {
            int q = __shfl_up_sync(0x0000ffffu, u, o, 16);
            if (lane >= o) u += q;
        }
        sw[lane] = u - t;  // exclusive warp offset
    }
    __syncthreads();
    if (n < N) {
        int off = g_pscan[blockIdx.x] + sw[wid] + v - dg;
        g_off[n] = off;
        g_cur[n] = off;
        g_inv[n] = 1.0f / fmaxf((float)dg, 1.0f);
    }
}

// ---------------- CSR fill ----------------------------------------------------
__global__ void k_fill(const void* __restrict__ ei, int E) {
    int is64 = g_is64;
    for (int e = blockIdx.x * blockDim.x + threadIdx.x; e < E;
         e += gridDim.x * blockDim.x) {
        int sN, d;
        if (is64) {
            const long long* p = (const long long*)ei;
            sN = (int)p[e];
            d = (int)p[(long)E + e];
        } else {
            const int* p = (const int*)ei;
            sN = p[e];
            d = p[(long)E + e];
        }
        int pos = atomicAdd(&g_cur[d], 1);
        g_csr[pos] = sN;
    }
}

// ---------------- gather-side mean aggregation (warp per node, 4x unroll) ---
template <int C>
__global__ void k_aggmean(const float* __restrict__ featx, int N) {
    int warp = (blockIdx.x * blockDim.x + threadIdx.x) >> 5;
    int lane = threadIdx.x & 31;
    if (warp >= N) return;
    int beg = g_off[warp];
    int end = beg + g_degi[warp];
    float iv = g_inv[warp];

    if (C == 64) {
        const float2* f2 = (const float2*)g_h1;
        float2 a0 = make_float2(0.f, 0.f), a1 = make_float2(0.f, 0.f);
        int j = beg;
        for (; j + 3 < end; j += 4) {
            int s0 = g_csr[j], s1 = g_csr[j + 1];
            int s2 = g_csr[j + 2], s3 = g_csr[j + 3];
            float2 p = f2[(long)s0 * 32 + lane];
            float2 q = f2[(long)s1 * 32 + lane];
            float2 r = f2[(long)s2 * 32 + lane];
            float2 w = f2[(long)s3 * 32 + lane];
            a0.x += p.x + q.x; a0.y += p.y + q.y;
            a1.x += r.x + w.x; a1.y += r.y + w.y;
        }
        for (; j < end; j++) {
            float2 p = f2[(long)g_csr[j] * 32 + lane];
            a0.x += p.x; a0.y += p.y;
        }
        ((float2*)g_agg)[(long)warp * 32 + lane] =
            make_float2((a0.x + a1.x) * iv, (a0.y + a1.y) * iv);
    } else {  // C == 32
        const float* feat = featx;
        float a0 = 0.f, a1 = 0.f;
        int j = beg;
        for (; j + 3 < end; j += 4) {
            int s0 = g_csr[j], s1 = g_csr[j + 1];
            int s2 = g_csr[j + 2], s3 = g_csr[j + 3];
            a0 += feat[(long)s0 * 32 + lane] + feat[(long)s1 * 32 + lane];
            a1 += feat[(long)s2 * 32 + lane] + feat[(long)s3 * 32 + lane];
        }
        for (; j < end; j++) a0 += feat[(long)g_csr[j] * 32 + lane];
        g_agg[(long)warp * 32 + lane] = (a0 + a1) * iv;
    }
}

// ---------------- fused SAGE layer GEMM (packed f32x2) -----------------------
// LAYER 1: out = relu(...) -> g_h1.
// LAYER 2: relu output consumed in-register by fused wl3/wr3 projection -> g_s,g_t
//          (h2 never materialized).
template <int KH, int LAYER>
__global__ void k_gemm(const float* __restrict__ fbx,
                       const float* __restrict__ wl,
                       const float* __restrict__ wr,
                       const float* __restrict__ bias,
                       const float* __restrict__ wl3,
                       const float* __restrict__ wr3, int N) {
    constexpr int COUT = 64;
    const float* fb = (LAYER == 1) ? fbx : g_h1;

    __shared__ float swl[KH][COUT];
    __shared__ float swr[KH][COUT];
    __shared__ float sl3[64], sr3[64];
    for (int i = threadIdx.x; i < KH * COUT; i += blockDim.x) {
        int o = i / KH, k = i % KH;
        swl[k][o] = wl[i];
        swr[k][o] = wr[i];
    }
    if (LAYER == 2 && threadIdx.x < 64) {
        sl3[threadIdx.x] = wl3[threadIdx.x];
        sr3[threadIdx.x] = wr3[threadIdx.x];
    }
    __syncthreads();

    int og = (threadIdx.x & 3) * 16;
    int nb = blockIdx.x * 128 + (threadIdx.x >> 2) * 4;

    int idx[4];
#pragma unroll
    for (int i = 0; i < 4; i++) idx[i] = min(nb + i, N - 1);

    // acc2[i][j] holds outputs (og+2j, og+2j+1) for node i, packed f32x2
    unsigned long long acc2[4][8];
#pragma unroll
    for (int i = 0; i < 4; i++)
#pragma unroll
        for (int j = 0; j < 8; j++) acc2[i][j] = 0ull;

    for (int k = 0; k < KH; k++) {
        unsigned long long va2[4], vb2[4];
#pragma unroll
        for (int i = 0; i < 4; i++) {
            float a = g_agg[(long)idx[i] * KH + k];
            float b = fb[(long)idx[i] * KH + k];
            va2[i] = pack2(a, a);
            vb2[i] = pack2(b, b);
        }
#pragma unroll
        for (int j = 0; j < 8; j++) {
            unsigned long long wl2 =
                *(const unsigned long long*)&swl[k][og + 2 * j];
            unsigned long long wr2 =
                *(const unsigned long long*)&swr[k][og + 2 * j];
#pragma unroll
            for (int i = 0; i < 4; i++) {
                fma2(acc2[i][j], va2[i], wl2);
                fma2(acc2[i][j], vb2[i], wr2);
            }
        }
    }

    const float2* bias2 = (const float2*)bias;
    float ps[4], pt[4];
#pragma unroll
    for (int i = 0; i < 4; i++) { ps[i] = 0.f; pt[i] = 0.f; }

#pragma unroll
    for (int i = 0; i < 4; i++) {
#pragma unroll
        for (int j = 0; j < 8; j++) {
            float2 v = unpack2(acc2[i][j]);
            float2 bv = bias2[og / 2 + j];
            float o0 = fmaxf(v.x + bv.x, 0.0f);
            float o1 = fmaxf(v.y + bv.y, 0.0f);
            if (LAYER == 1) {
                if (nb + i < N)
                    *(float2*)(g_h1 + (long)(nb + i) * 64 + og + 2 * j) =
                        make_float2(o0, o1);
            } else {
                ps[i] += o0 * sl3[og + 2 * j] + o1 * sl3[og + 2 * j + 1];
                pt[i] += o0 * sr3[og + 2 * j] + o1 * sr3[og + 2 * j + 1];
            }
        }
    }

    if (LAYER == 2) {
        // reduce across the 4 lanes (same node group: lanes differ in bits 0-1)
#pragma unroll
        for (int i = 0; i < 4; i++) {
#pragma unroll
            for (int o = 1; o <= 2; o <<= 1) {
                ps[i] += __shfl_xor_sync(0xffffffffu, ps[i], o);
                pt[i] += __shfl_xor_sync(0xffffffffu, pt[i], o);
            }
        }
        if ((threadIdx.x & 3) == 0) {
#pragma unroll
            for (int i = 0; i < 4; i++) {
                if (nb + i < N) {
                    g_s[nb + i] = ps[i];
                    g_t[nb + i] = pt[i];
                }
            }
        }
    }
}

// ---------------- layer-3: CSR scalar aggregation + sigmoid -----------------
__global__ void k_out3(const float* __restrict__ b3, float* __restrict__ out,
                       int N) {
    int warp = (blockIdx.x * blockDim.x + threadIdx.x) >> 5;
    int lane = threadIdx.x & 31;
    if (warp >= N) return;
    int beg = g_off[warp];
    int end = beg + g_degi[warp];
    float acc = 0.0f;
    for (int j = beg + lane; j < end; j += 32) acc += g_s[g_csr[j]];
#pragma unroll
    for (int o = 16; o > 0; o >>= 1)
        acc += __shfl_xor_sync(0xffffffffu, acc, o);
    if (lane == 0) {
        float z = acc * g_inv[warp] + b3[0] + g_t[warp];
        out[warp] = 1.0f / (1.0f + expf(-z));
    }
}

// ---------------- launch -----------------------------------------------------
extern "C" void kernel_launch(void* const* d_in, const int* in_sizes, int n_in,
                              void* d_out, int out_size) {
    const float* x   = (const float*)d_in[0];
    const void*  ei  = d_in[1];
    const float* wl1 = (const float*)d_in[2];
    const float* wr1 = (const float*)d_in[3];
    const float* b1  = (const float*)d_in[4];
    const float* wl2 = (const float*)d_in[5];
    const float* wr2 = (const float*)d_in[6];
    const float* b2  = (const float*)d_in[7];
    const float* wl3 = (const float*)d_in[8];
    const float* wr3 = (const float*)d_in[9];
    const float* b3  = (const float*)d_in[10];
    float* out = (float*)d_out;

    int N = in_sizes[0] / 32;
    int E = in_sizes[1] / 2;
    int NB = (N + SCAN_CH - 1) / SCAN_CH;

    // ---- preprocessing: CSR build ----
    k_detect<<<1, 1>>>((const int*)ei);
    k_zero_degi<<<(N + 255) / 256, 256>>>(N);
    k_count<<<(E + 255) / 256, 256>>>(ei, E);
    k_scan1<<<NB, SCAN_CH>>>(N);
    k_scan2<<<1, MAXNB>>>(NB);
    k_scan3<<<NB, SCAN_CH>>>(N);
    k_fill<<<(E + 255) / 256, 256>>>(ei, E);

    // ---- layer 1 ----
    k_aggmean<32><<<(N * 32 + 255) / 256, 256>>>(x, N);
    k_gemm<32, 1><<<(N + 127) / 128, 128>>>(x, wl1, wr1, b1, wl3, wr3, N);

    // ---- layer 2 (GEMM with fused wl3/wr3 projection; h2 never stored) ----
    k_aggmean<64><<<(N * 32 + 255) / 256, 256>>>(nullptr, N);
    k_gemm<64, 2><<<(N + 127) / 128, 128>>>(nullptr, wl2, wr2, b2, wl3, wr3, N);

    // ---- layer 3 output ----
    k_out3<<<(N * 32 + 255) / 256, 256>>>(b3, out, N);
}

// round 5
// speedup vs baseline: 1.4882x; 1.0277x over previous
#include <cuda_runtime.h>
#include <math.h>

#define MAXN 100000
#define MAXE 1600000
#define SCAN_CH 512
#define MAXNB 256   // >= ceil(MAXN/SCAN_CH) = 196

// ---------------- scratch (device-code-only globals; see round-2 postmortem)
__device__ __align__(16) float g_agg[(size_t)MAXN * 64];
__device__ __align__(16) float g_h1[(size_t)MAXN * 64];
__device__ float g_inv[MAXN];
__device__ float g_s[MAXN];
__device__ float g_t[MAXN];
__device__ int   g_degi[MAXN];
__device__ int   g_off[MAXN];
__device__ int   g_cur[MAXN];
__device__ int   g_csr[MAXE];
__device__ int   g_part[MAXNB];
__device__ int   g_pscan[MAXNB];
__device__ int   g_is64;

// ---------------- packed f32x2 helpers ---------------------------------------
__device__ __forceinline__ unsigned long long pack2(float x, float y) {
    unsigned long long r;
    asm("mov.b64 %0, {%1, %2};" : "=l"(r) : "f"(x), "f"(y));
    return r;
}
__device__ __forceinline__ void fma2(unsigned long long& d,
                                     unsigned long long a,
                                     unsigned long long b) {
    asm("fma.rn.f32x2 %0, %1, %2, %0;" : "+l"(d) : "l"(a), "l"(b));
}
__device__ __forceinline__ float2 unpack2(unsigned long long r) {
    float2 f;
    asm("mov.b64 {%0, %1}, %2;" : "=f"(f.x), "=f"(f.y) : "l"(r));
    return f;
}

// ---------------- dtype detect: int64 vs int32 edge_index -------------------
__global__ void k_detect(const int* __restrict__ ei32) {
    int is64 = 1;
#pragma unroll
    for (int i = 1; i < 32; i += 2)
        if (ei32[i] != 0) is64 = 0;
    g_is64 = is64;
}

__global__ void k_zero_degi(int N) {
    for (int i = blockIdx.x * blockDim.x + threadIdx.x; i < N;
         i += gridDim.x * blockDim.x)
        g_degi[i] = 0;
}

// ---------------- degree histogram ------------------------------------------
__global__ void k_count(const void* __restrict__ ei, int E) {
    int is64 = g_is64;
    for (int e = blockIdx.x * blockDim.x + threadIdx.x; e < E;
         e += gridDim.x * blockDim.x) {
        int d;
        if (is64) d = (int)((const long long*)ei)[(long)E + e];
        else      d = ((const int*)ei)[(long)E + e];
        atomicAdd(&g_degi[d], 1);
    }
}

// ---------------- scan phase 1: per-chunk sums (warp shuffles) --------------
__global__ void k_scan1(int N) {
    __shared__ int sw[16];
    int tid = threadIdx.x;
    int n = blockIdx.x * SCAN_CH + tid;
    int v = (n < N) ? g_degi[n] : 0;
#pragma unroll
    for (int o = 16; o > 0; o >>= 1) v += __shfl_xor_sync(0xffffffffu, v, o);
    if ((tid & 31) == 0) sw[tid >> 5] = v;
    __syncthreads();
    if (tid < 16) {
        int t = sw[tid];
#pragma unroll
        for (int o = 8; o > 0; o >>= 1)
            t += __shfl_xor_sync(0x0000ffffu, t, o, 16);
        if (tid == 0) g_part[blockIdx.x] = t;
    }
}

// ---------------- scan phase 2: scan of 196 partials -------------------------
__global__ void k_scan2(int NB) {
    __shared__ int s[MAXNB];
    int tid = threadIdx.x;
    int v = (tid < NB) ? g_part[tid] : 0;
    s[tid] = v;
    __syncthreads();
    for (int ofs = 1; ofs < MAXNB; ofs <<= 1) {
        int t = (tid >= ofs) ? s[tid - ofs] : 0;
        __syncthreads();
        s[tid] += t;
        __syncthreads();
    }
    if (tid < NB) g_pscan[tid] = s[tid] - v;
}

// ---------------- scan phase 3: intra-chunk exclusive scan (shuffles) -------
__global__ void k_scan3(int N) {
    __shared__ int sw[16];
    int tid = threadIdx.x;
    int lane = tid & 31, wid = tid >> 5;
    int n = blockIdx.x * SCAN_CH + tid;
    int dg = (n < N) ? g_degi[n] : 0;
    int v = dg;
#pragma unroll
    for (int o = 1; o < 32; o <<= 1) {
        int t = __shfl_up_sync(0xffffffffu, v, o);
        if (lane >= o) v += t;
    }
    if (lane == 31) sw[wid] = v;
    __syncthreads();
    if (wid == 0 && lane < 16) {
        int t = sw[lane];
        int u = t;
#pragma unroll
        for (int o = 1; o < 16; o <<= 1) {
            int q = __shfl_up_sync(0x0000ffffu, u, o, 16);
            if (lane >= o) u += q;
        }
        sw[lane] = u - t;  // exclusive warp offset
    }
    __syncthreads();
    if (n < N) {
        int off = g_pscan[blockIdx.x] + sw[wid] + v - dg;
        g_off[n] = off;
        g_cur[n] = off;
        g_inv[n] = 1.0f / fmaxf((float)dg, 1.0f);
    }
}

// ---------------- CSR fill ----------------------------------------------------
__global__ void k_fill(const void* __restrict__ ei, int E) {
    int is64 = g_is64;
    for (int e = blockIdx.x * blockDim.x + threadIdx.x; e < E;
         e += gridDim.x * blockDim.x) {
        int sN, d;
        if (is64) {
            const long long* p = (const long long*)ei;
            sN = (int)p[e];
            d = (int)p[(long)E + e];
        } else {
            const int* p = (const int*)ei;
            sN = p[e];
            d = p[(long)E + e];
        }
        int pos = atomicAdd(&g_cur[d], 1);
        g_csr[pos] = sN;
    }
}

// ---------------- gather-side mean aggregation (warp per node, 4x unroll) ---
template <int C>
__global__ void k_aggmean(const float* __restrict__ featx, int N) {
    int warp = (blockIdx.x * blockDim.x + threadIdx.x) >> 5;
    int lane = threadIdx.x & 31;
    if (warp >= N) return;
    int beg = g_off[warp];
    int end = beg + g_degi[warp];
    float iv = g_inv[warp];

    if (C == 64) {
        const float2* f2 = (const float2*)g_h1;
        float2 a0 = make_float2(0.f, 0.f), a1 = make_float2(0.f, 0.f);
        int j = beg;
        for (; j + 3 < end; j += 4) {
            int s0 = g_csr[j], s1 = g_csr[j + 1];
            int s2 = g_csr[j + 2], s3 = g_csr[j + 3];
            float2 p = f2[(long)s0 * 32 + lane];
            float2 q = f2[(long)s1 * 32 + lane];
            float2 r = f2[(long)s2 * 32 + lane];
            float2 w = f2[(long)s3 * 32 + lane];
            a0.x += p.x + q.x; a0.y += p.y + q.y;
            a1.x += r.x + w.x; a1.y += r.y + w.y;
        }
        for (; j < end; j++) {
            float2 p = f2[(long)g_csr[j] * 32 + lane];
            a0.x += p.x; a0.y += p.y;
        }
        ((float2*)g_agg)[(long)warp * 32 + lane] =
            make_float2((a0.x + a1.x) * iv, (a0.y + a1.y) * iv);
    } else {  // C == 32
        const float* feat = featx;
        float a0 = 0.f, a1 = 0.f;
        int j = beg;
        for (; j + 3 < end; j += 4) {
            int s0 = g_csr[j], s1 = g_csr[j + 1];
            int s2 = g_csr[j + 2], s3 = g_csr[j + 3];
            a0 += feat[(long)s0 * 32 + lane] + feat[(long)s1 * 32 + lane];
            a1 += feat[(long)s2 * 32 + lane] + feat[(long)s3 * 32 + lane];
        }
        for (; j < end; j++) a0 += feat[(long)g_csr[j] * 32 + lane];
        g_agg[(long)warp * 32 + lane] = (a0 + a1) * iv;
    }
}

// ---------------- fused SAGE layer GEMM (packed f32x2) -----------------------
// LAYER 1: out = relu(...) -> g_h1.
// LAYER 2: relu output consumed in-register by fused wl3/wr3 projection -> g_s,g_t
//          (h2 never materialized).
template <int KH, int LAYER>
__global__ void k_gemm(const float* __restrict__ fbx,
                       const float* __restrict__ wl,
                       const float* __restrict__ wr,
                       const float* __restrict__ bias,
                       const float* __restrict__ wl3,
                       const float* __restrict__ wr3, int N) {
    constexpr int COUT = 64;
    const float* fb = (LAYER == 1) ? fbx : g_h1;

    __shared__ float swl[KH][COUT];
    __shared__ float swr[KH][COUT];
    __shared__ float sl3[64], sr3[64];
    for (int i = threadIdx.x; i < KH * COUT; i += blockDim.x) {
        int o = i / KH, k = i % KH;
        swl[k][o] = wl[i];
        swr[k][o] = wr[i];
    }
    if (LAYER == 2 && threadIdx.x < 64) {
        sl3[threadIdx.x] = wl3[threadIdx.x];
        sr3[threadIdx.x] = wr3[threadIdx.x];
    }
    __syncthreads();

    int og = (threadIdx.x & 3) * 16;
    int nb = blockIdx.x * 128 + (threadIdx.x >> 2) * 4;

    int idx[4];
#pragma unroll
    for (int i = 0; i < 4; i++) idx[i] = min(nb + i, N - 1);

    // acc2[i][j] holds outputs (og+2j, og+2j+1) for node i, packed f32x2
    unsigned long long acc2[4][8];
#pragma unroll
    for (int i = 0; i < 4; i++)
#pragma unroll
        for (int j = 0; j < 8; j++) acc2[i][j] = 0ull;

    for (int k = 0; k < KH; k++) {
        unsigned long long va2[4], vb2[4];
#pragma unroll
        for (int i = 0; i < 4; i++) {
            float a = g_agg[(long)idx[i] * KH + k];
            float b = fb[(long)idx[i] * KH + k];
            va2[i] = pack2(a, a);
            vb2[i] = pack2(b, b);
        }
#pragma unroll
        for (int j = 0; j < 8; j++) {
            unsigned long long wl2 =
                *(const unsigned long long*)&swl[k][og + 2 * j];
            unsigned long long wr2 =
                *(const unsigned long long*)&swr[k][og + 2 * j];
#pragma unroll
            for (int i = 0; i < 4; i++) {
                fma2(acc2[i][j], va2[i], wl2);
                fma2(acc2[i][j], vb2[i], wr2);
            }
        }
    }

    const float2* bias2 = (const float2*)bias;
    float ps[4], pt[4];
#pragma unroll
    for (int i = 0; i < 4; i++) { ps[i] = 0.f; pt[i] = 0.f; }

#pragma unroll
    for (int i = 0; i < 4; i++) {
#pragma unroll
        for (int j = 0; j < 8; j++) {
            float2 v = unpack2(acc2[i][j]);
            float2 bv = bias2[og / 2 + j];
            float o0 = fmaxf(v.x + bv.x, 0.0f);
            float o1 = fmaxf(v.y + bv.y, 0.0f);
            if (LAYER == 1) {
                if (nb + i < N)
                    *(float2*)(g_h1 + (long)(nb + i) * 64 + og + 2 * j) =
                        make_float2(o0, o1);
            } else {
                ps[i] += o0 * sl3[og + 2 * j] + o1 * sl3[og + 2 * j + 1];
                pt[i] += o0 * sr3[og + 2 * j] + o1 * sr3[og + 2 * j + 1];
            }
        }
    }

    if (LAYER == 2) {
        // reduce across the 4 lanes (same node group: lanes differ in bits 0-1)
#pragma unroll
        for (int i = 0; i < 4; i++) {
#pragma unroll
            for (int o = 1; o <= 2; o <<= 1) {
                ps[i] += __shfl_xor_sync(0xffffffffu, ps[i], o);
                pt[i] += __shfl_xor_sync(0xffffffffu, pt[i], o);
            }
        }
        if ((threadIdx.x & 3) == 0) {
#pragma unroll
            for (int i = 0; i < 4; i++) {
                if (nb + i < N) {
                    g_s[nb + i] = ps[i];
                    g_t[nb + i] = pt[i];
                }
            }
        }
    }
}

// ---------------- layer-3: CSR scalar aggregation + sigmoid -----------------
__global__ void k_out3(const float* __restrict__ b3, float* __restrict__ out,
                       int N) {
    int warp = (blockIdx.x * blockDim.x + threadIdx.x) >> 5;
    int lane = threadIdx.x & 31;
    if (warp >= N) return;
    int beg = g_off[warp];
    int end = beg + g_degi[warp];
    float acc = 0.0f;
    for (int j = beg + lane; j < end; j += 32) acc += g_s[g_csr[j]];
#pragma unroll
    for (int o = 16; o > 0; o >>= 1)
        acc += __shfl_xor_sync(0xffffffffu, acc, o);
    if (lane == 0) {
        float z = acc * g_inv[warp] + b3[0] + g_t[warp];
        out[warp] = 1.0f / (1.0f + expf(-z));
    }
}

// ---------------- launch -----------------------------------------------------
extern "C" void kernel_launch(void* const* d_in, const int* in_sizes, int n_in,
                              void* d_out, int out_size) {
    const float* x   = (const float*)d_in[0];
    const void*  ei  = d_in[1];
    const float* wl1 = (const float*)d_in[2];
    const float* wr1 = (const float*)d_in[3];
    const float* b1  = (const float*)d_in[4];
    const float* wl2 = (const float*)d_in[5];
    const float* wr2 = (const float*)d_in[6];
    const float* b2  = (const float*)d_in[7];
    const float* wl3 = (const float*)d_in[8];
    const float* wr3 = (const float*)d_in[9];
    const float* b3  = (const float*)d_in[10];
    float* out = (float*)d_out;

    int N = in_sizes[0] / 32;
    int E = in_sizes[1] / 2;
    int NB = (N + SCAN_CH - 1) / SCAN_CH;

    // ---- preprocessing: CSR build ----
    k_detect<<<1, 1>>>((const int*)ei);
    k_zero_degi<<<(N + 255) / 256, 256>>>(N);
    k_count<<<(E + 255) / 256, 256>>>(ei, E);
    k_scan1<<<NB, SCAN_CH>>>(N);
    k_scan2<<<1, MAXNB>>>(NB);
    k_scan3<<<NB, SCAN_CH>>>(N);
    k_fill<<<(E + 255) / 256, 256>>>(ei, E);

    // ---- layer 1 ----
    k_aggmean<32><<<(N * 32 + 255) / 256, 256>>>(x, N);
    k_gemm<32, 1><<<(N + 127) / 128, 128>>>(x, wl1, wr1, b1, wl3, wr3, N);

    // ---- layer 2 (GEMM with fused wl3/wr3 projection; h2 never stored) ----
    k_aggmean<64><<<(N * 32 + 255) / 256, 256>>>(nullptr, N);
    k_gemm<64, 2><<<(N + 127) / 128, 128>>>(nullptr, wl2, wr2, b2, wl3, wr3, N);

    // ---- layer 3 output ----
    k_out3<<<(N * 32 + 255) / 256, 256>>>(b3, out, N);
}